// round 10
// baseline (speedup 1.0000x reference)
#include <cuda_runtime.h>
#include <cuda_fp16.h>
#include <cstdint>

#define IN_F   3072
#define OUT_F  9216
#define RANK   32
#define MROWS  4096
#define NG     48            // K groups of 64
#define TM     256
#define TN     128
#define PITCH  80

__device__ uint8_t g_Aq[(size_t)MROWS * IN_F];     // e4m3-coded int4 activations
__device__ float   g_Asc[(size_t)MROWS * NG];      // per (m, group) act scale
__device__ uint8_t g_Bq[(size_t)OUT_F * IN_F];     // e4m3-coded weight nibbles
__device__ __half  g_ALora[(size_t)MROWS * RANK];
__device__ __half  g_BLora[(size_t)OUT_F * RANK];

__device__ __forceinline__ uint32_t smem_u32(const void* p) {
    uint32_t a;
    asm("{ .reg .u64 t; cvta.to.shared.u64 t, %1; cvt.u32.u64 %0, t; }" : "=r"(a) : "l"(p));
    return a;
}

#define CP16(sa, gp) \
    asm volatile("cp.async.cg.shared.global [%0], [%1], 16;" :: "r"(sa), "l"(gp))
#define CP_COMMIT() asm volatile("cp.async.commit_group;")
#define CP_WAIT0()  asm volatile("cp.async.wait_group 0;")
#define CP_WAIT1()  asm volatile("cp.async.wait_group 1;")

// fp8 e4m3 MMA, f32 accum. _Z: c = zero regs; _A: accumulate in place.
#define MMAF8_Z(d, a, b0, b1, z) \
    asm volatile("mma.sync.aligned.m16n8k32.row.col.f32.e4m3.e4m3.f32 " \
        "{%0,%1,%2,%3}, {%4,%5,%6,%7}, {%8,%9}, {%10,%11,%12,%13};" \
        : "=f"((d)[0]), "=f"((d)[1]), "=f"((d)[2]), "=f"((d)[3]) \
        : "r"((a)[0]), "r"((a)[1]), "r"((a)[2]), "r"((a)[3]), "r"(b0), "r"(b1), \
          "f"(z), "f"(z), "f"(z), "f"(z))
#define MMAF8_A(d, a, b0, b1) \
    asm volatile("mma.sync.aligned.m16n8k32.row.col.f32.e4m3.e4m3.f32 " \
        "{%0,%1,%2,%3}, {%4,%5,%6,%7}, {%8,%9}, {%0,%1,%2,%3};" \
        : "+f"((d)[0]), "+f"((d)[1]), "+f"((d)[2]), "+f"((d)[3]) \
        : "r"((a)[0]), "r"((a)[1]), "r"((a)[2]), "r"((a)[3]), "r"(b0), "r"(b1))

#define MMA16816(d, a, b0, b1) \
    asm volatile("mma.sync.aligned.m16n8k16.row.col.f32.f16.f16.f32 " \
        "{%0,%1,%2,%3}, {%4,%5,%6,%7}, {%8,%9}, {%0,%1,%2,%3};" \
        : "+f"((d)[0]), "+f"((d)[1]), "+f"((d)[2]), "+f"((d)[3]) \
        : "r"((a)[0]), "r"((a)[1]), "r"((a)[2]), "r"((a)[3]), "r"(b0), "r"(b1))

// exact e4m3 encoding of integers in [-8, 8]
__device__ __forceinline__ uint8_t int_to_e4m3(int q) {
    int neg = q < 0;
    int a = neg ? -q : q;
    const uint64_t tbl = 0x504E4C4A48444038ULL;   // abs 1..8
    uint8_t b = a == 0 ? 0 : (uint8_t)(tbl >> ((a - 1) * 8));
    return b | (neg ? 0x80 : 0);
}

// ---------- kernel 1: activation group-quant -> e4m3 ints + scales ---------
__global__ void __launch_bounds__(384) quant_act_kernel(
    const float* __restrict__ x, const float* __restrict__ smooth)
{
    int m = blockIdx.x, t = threadIdx.x;
    const float4* xp = reinterpret_cast<const float4*>(x + (size_t)m * IN_F + t * 8);
    const float4* sp = reinterpret_cast<const float4*>(smooth + t * 8);
    float4 x0 = xp[0], x1 = xp[1], s0 = sp[0], s1 = sp[1];
    float xs[8];
    xs[0] = __fdiv_rn(x0.x, s0.x); xs[1] = __fdiv_rn(x0.y, s0.y);
    xs[2] = __fdiv_rn(x0.z, s0.z); xs[3] = __fdiv_rn(x0.w, s0.w);
    xs[4] = __fdiv_rn(x1.x, s1.x); xs[5] = __fdiv_rn(x1.y, s1.y);
    xs[6] = __fdiv_rn(x1.z, s1.z); xs[7] = __fdiv_rn(x1.w, s1.w);
    float am = 0.f;
    #pragma unroll
    for (int i = 0; i < 8; i++) am = fmaxf(am, fabsf(xs[i]));
    am = fmaxf(am, __shfl_xor_sync(~0u, am, 1));
    am = fmaxf(am, __shfl_xor_sync(~0u, am, 2));
    am = fmaxf(am, __shfl_xor_sync(~0u, am, 4));
    float ascale = fmaxf(__fdiv_rn(am, 7.0f), 1e-8f);
    if ((t & 7) == 0) g_Asc[(size_t)m * NG + (t >> 3)] = ascale;
    union { uint2 u; uint8_t b[8]; } o;
    #pragma unroll
    for (int i = 0; i < 8; i++) {
        float q = rintf(__fdiv_rn(xs[i], ascale));
        q = fminf(fmaxf(q, -8.f), 7.f);
        o.b[i] = int_to_e4m3((int)q);
    }
    *reinterpret_cast<uint2*>(g_Aq + (size_t)m * IN_F + t * 8) = o.u;
}

// ---------- kernel 2: lora_act = (x/smooth) @ lora_down -> fp16 ------------
__global__ void __launch_bounds__(256) lora_act_kernel(
    const float* __restrict__ x, const float* __restrict__ smooth,
    const float* __restrict__ ldw)
{
    __shared__ float xs_s[32][32];
    __shared__ float ld_s[32][32];
    int m0 = blockIdx.x * 32;
    int t = threadIdx.x, lane = t & 31, w = t >> 5, rb = w * 4;
    float acc[4] = {0.f, 0.f, 0.f, 0.f};
    for (int k0 = 0; k0 < IN_F; k0 += 32) {
        #pragma unroll
        for (int i = 0; i < 4; i++) {
            int idx = i * 256 + t, kk = idx & 31, row = idx >> 5;
            xs_s[row][kk] = __fdiv_rn(x[(size_t)(m0 + row) * IN_F + k0 + kk], smooth[k0 + kk]);
        }
        #pragma unroll
        for (int i = 0; i < 4; i++) {
            int idx = i * 256 + t, r = idx & 31, kk = idx >> 5;
            ld_s[kk][r] = ldw[(size_t)(k0 + kk) * RANK + r];
        }
        __syncthreads();
        #pragma unroll
        for (int kk = 0; kk < 32; kk += 4) {
            float l0 = ld_s[kk][lane], l1 = ld_s[kk+1][lane];
            float l2 = ld_s[kk+2][lane], l3 = ld_s[kk+3][lane];
            #pragma unroll
            for (int rr = 0; rr < 4; rr++) {
                float4 a = *reinterpret_cast<const float4*>(&xs_s[rb + rr][kk]);
                acc[rr] += a.x * l0 + a.y * l1 + a.z * l2 + a.w * l3;
            }
        }
        __syncthreads();
    }
    #pragma unroll
    for (int rr = 0; rr < 4; rr++)
        g_ALora[(size_t)(m0 + rb + rr) * RANK + lane] = __float2half_rn(acc[rr]);
}

// ---------- kernel 3: weight nibbles -> e4m3 ints ---------------------------
__global__ void __launch_bounds__(256) wdeq_kernel(const int* __restrict__ qw)
{
    int tid = blockIdx.x * blockDim.x + threadIdx.x;
    if (tid >= OUT_F * 192) return;
    int n = tid / 192, c = tid - n * 192;
    const int4* q4 = reinterpret_cast<const int4*>(qw + (size_t)n * (IN_F / 2) + c * 8);
    int4 v0 = q4[0], v1 = q4[1];
    int vals[8] = {v0.x, v0.y, v0.z, v0.w, v1.x, v1.y, v1.z, v1.w};
    union { uint4 u; uint8_t b[16]; } o;
    #pragma unroll
    for (int j = 0; j < 8; j++) {
        int b = vals[j];
        o.b[2*j]   = int_to_e4m3(((b & 15) ^ 8) - 8);
        o.b[2*j+1] = int_to_e4m3(b >> 4);
    }
    *reinterpret_cast<uint4*>(g_Bq + (size_t)n * IN_F + c * 16) = o.u;
}

// ---------- kernel 4: lora_up -> fp16 ---------------------------------------
__global__ void __launch_bounds__(256) wlora_kernel(const float* __restrict__ lu)
{
    int n = blockIdx.x * blockDim.x + threadIdx.x;
    if (n >= OUT_F) return;
    const float4* src = reinterpret_cast<const float4*>(lu + (size_t)n * RANK);
    union { uint4 u[4]; __half h[32]; } o;
    #pragma unroll
    for (int i = 0; i < 8; i++) {
        float4 v = src[i];
        o.h[4*i+0] = __float2half_rn(v.x); o.h[4*i+1] = __float2half_rn(v.y);
        o.h[4*i+2] = __float2half_rn(v.z); o.h[4*i+3] = __float2half_rn(v.w);
    }
    uint4* dst = reinterpret_cast<uint4*>(g_BLora + (size_t)n * RANK);
    #pragma unroll
    for (int i = 0; i < 4; i++) dst[i] = o.u[i];
}

__global__ void dummy_kernel() {}   // makes gemm the 6th launch for ncu -s 5

// ---------- kernel 5: fp8 MMA GEMM 256x128 + lora HMMA + fused epilogue ----
// dyn smem layout (bytes)
#define OFF_A   0                         // 3 x 256*80
#define OFF_B   61440                     // 3 x 128*80
#define OFF_LA  92160                     // 256*80
#define OFF_LB  112640                    // 128*80
#define OFF_AS  122880                    // 48*256 f32
#define OFF_WS  172032                    // 48*128 f32
#define OFF_SS  196608                    // 256*2 f32
#define SMEM_TOTAL 198656

__global__ void __launch_bounds__(256, 1) gemm_kernel(
    const float* __restrict__ ws,   const float* __restrict__ bias,
    const float* __restrict__ nq,   const float* __restrict__ nk,
    const float* __restrict__ rope, float* __restrict__ out)
{
    extern __shared__ __align__(128) uint8_t dsm[];
    float* sAs = reinterpret_cast<float*>(dsm + OFF_AS);
    float* sWs = reinterpret_cast<float*>(dsm + OFF_WS);
    float* sSS = reinterpret_cast<float*>(dsm + OFF_SS);

    int t = threadIdx.x, wid = t >> 5, lane = t & 31;
    int wm = wid >> 1, wn = wid & 1;
    int quad = lane >> 2, qlane = lane & 3;
    int n0 = blockIdx.x * TN, m0 = blockIdx.y * TM;

    uint32_t sb = smem_u32(dsm);
    const uint8_t* Ag = g_Aq + (size_t)m0 * IN_F;
    const uint8_t* Bg = g_Bq + (size_t)n0 * IN_F;

    // per-thread cp.async segments (stage tiles: K-chunk 64 bytes)
    uint32_t soA[4], soB[2];
    size_t gaA[4], gaB[2];
    #pragma unroll
    for (int i = 0; i < 4; i++) {
        int seg = i * 256 + t, row = seg >> 2, s = seg & 3;
        soA[i] = (uint32_t)(row * PITCH + s * 16);
        gaA[i] = (size_t)row * IN_F + s * 16;
    }
    #pragma unroll
    for (int i = 0; i < 2; i++) {
        int seg = i * 256 + t, row = seg >> 2, s = seg & 3;
        soB[i] = (uint32_t)(row * PITCH + s * 16);
        gaB[i] = (size_t)row * IN_F + s * 16;
    }

    // scale tiles: as[48][256], ws[48][128]
    for (int g = 0; g < NG; g++)
        sAs[g * 256 + t] = g_Asc[(size_t)(m0 + t) * NG + g];
    #pragma unroll
    for (int i = 0; i < 24; i++) {
        int idx = i * 256 + t, g = idx >> 7, col = idx & 127;
        sWs[idx] = ws[(size_t)g * OUT_F + n0 + col];
    }

    // prologue group 1: lora tiles + stage 0
    {
        const uint8_t* LAg = reinterpret_cast<const uint8_t*>(g_ALora) + (size_t)m0 * 64;
        const uint8_t* LBg = reinterpret_cast<const uint8_t*>(g_BLora) + (size_t)n0 * 64;
        #pragma unroll
        for (int i = 0; i < 4; i++) {
            int seg = i * 256 + t, row = seg >> 2, s = seg & 3;
            CP16(sb + OFF_LA + row * PITCH + s * 16, LAg + (size_t)row * 64 + s * 16);
        }
        #pragma unroll
        for (int i = 0; i < 2; i++) {
            int seg = i * 256 + t, row = seg >> 2, s = seg & 3;
            CP16(sb + OFF_LB + row * PITCH + s * 16, LBg + (size_t)row * 64 + s * 16);
        }
        #pragma unroll
        for (int i = 0; i < 4; i++) CP16(sb + OFF_A + soA[i], Ag + gaA[i]);
        #pragma unroll
        for (int i = 0; i < 2; i++) CP16(sb + OFF_B + soB[i], Bg + gaB[i]);
        CP_COMMIT();
    }
    // prologue group 2: stage 1
    {
        #pragma unroll
        for (int i = 0; i < 4; i++) CP16(sb + OFF_A + 20480 + soA[i], Ag + gaA[i] + 64);
        #pragma unroll
        for (int i = 0; i < 2; i++) CP16(sb + OFF_B + 10240 + soB[i], Bg + gaB[i] + 64);
        CP_COMMIT();
    }

    float acc[4][8][4];
    #pragma unroll
    for (int mi = 0; mi < 4; mi++)
        #pragma unroll
        for (int ni = 0; ni < 8; ni++)
            #pragma unroll
            for (int j = 0; j < 4; j++) acc[mi][ni][j] = 0.f;

    float fz = 0.f;
    int stage = 0;
    for (int g = 0; g < NG; g++) {
        if (g < NG - 1) CP_WAIT1(); else CP_WAIT0();
        __syncthreads();

        if (g + 2 < NG) {
            int st2 = stage + 2 >= 3 ? stage - 1 : stage + 2;
            uint32_t ab = sb + OFF_A + st2 * 20480, bb = sb + OFF_B + st2 * 10240;
            int ko = (g + 2) * 64;
            #pragma unroll
            for (int i = 0; i < 4; i++) CP16(ab + soA[i], Ag + gaA[i] + ko);
            #pragma unroll
            for (int i = 0; i < 2; i++) CP16(bb + soB[i], Bg + gaB[i] + ko);
            CP_COMMIT();
        }

        const uint8_t* Asm = dsm + OFF_A + stage * 20480;
        const uint8_t* Bsm = dsm + OFF_B + stage * 10240;

        float asr[4][2];
        #pragma unroll
        for (int mi = 0; mi < 4; mi++) {
            int r = wm * 64 + mi * 16 + quad;
            asr[mi][0] = sAs[g * 256 + r];
            asr[mi][1] = sAs[g * 256 + r + 8];
        }
        float wsc[8][2];
        #pragma unroll
        for (int ni = 0; ni < 8; ni++) {
            float2 w = *reinterpret_cast<const float2*>(
                sWs + g * 128 + wn * 64 + ni * 8 + qlane * 2);
            wsc[ni][0] = w.x; wsc[ni][1] = w.y;
        }

        uint32_t af[4][2][4];
        #pragma unroll
        for (int mi = 0; mi < 4; mi++)
            #pragma unroll
            for (int ks = 0; ks < 2; ks++) {
                int base = (wm * 64 + mi * 16 + quad) * PITCH + ks * 32 + qlane * 4;
                af[mi][ks][0] = *reinterpret_cast<const uint32_t*>(Asm + base);
                af[mi][ks][1] = *reinterpret_cast<const uint32_t*>(Asm + base + 8 * PITCH);
                af[mi][ks][2] = *reinterpret_cast<const uint32_t*>(Asm + base + 16);
                af[mi][ks][3] = *reinterpret_cast<const uint32_t*>(Asm + base + 8 * PITCH + 16);
            }
        uint32_t bf[8][2][2];
        #pragma unroll
        for (int ni = 0; ni < 8; ni++)
            #pragma unroll
            for (int ks = 0; ks < 2; ks++) {
                int base = (wn * 64 + ni * 8 + quad) * PITCH + ks * 32 + qlane * 4;
                bf[ni][ks][0] = *reinterpret_cast<const uint32_t*>(Bsm + base);
                bf[ni][ks][1] = *reinterpret_cast<const uint32_t*>(Bsm + base + 16);
            }

        #pragma unroll
        for (int mi = 0; mi < 4; mi++)
            #pragma unroll
            for (int ni = 0; ni < 8; ni++) {
                float tp[4];
                MMAF8_Z(tp, af[mi][0], bf[ni][0][0], bf[ni][0][1], fz);
                MMAF8_A(tp, af[mi][1], bf[ni][1][0], bf[ni][1][1]);
                float s00 = asr[mi][0] * wsc[ni][0];
                float s01 = asr[mi][0] * wsc[ni][1];
                float s10 = asr[mi][1] * wsc[ni][0];
                float s11 = asr[mi][1] * wsc[ni][1];
                acc[mi][ni][0] += s00 * tp[0];
                acc[mi][ni][1] += s01 * tp[1];
                acc[mi][ni][2] += s10 * tp[2];
                acc[mi][ni][3] += s11 * tp[3];
            }
        stage = stage + 1 >= 3 ? 0 : stage + 1;
    }

    // ---- LoRA: 32 fp16 K-columns via HMMA into the f32 accumulators ----
    {
        const uint8_t* LAs = dsm + OFF_LA;
        const uint8_t* LBs = dsm + OFF_LB;
        #pragma unroll
        for (int ks = 0; ks < 2; ks++) {
            uint32_t a[4][4];
            #pragma unroll
            for (int mi = 0; mi < 4; mi++) {
                int base = (wm * 64 + mi * 16 + quad) * PITCH + ks * 32 + qlane * 4;
                a[mi][0] = *reinterpret_cast<const uint32_t*>(LAs + base);
                a[mi][1] = *reinterpret_cast<const uint32_t*>(LAs + base + 8 * PITCH);
                a[mi][2] = *reinterpret_cast<const uint32_t*>(LAs + base + 16);
                a[mi][3] = *reinterpret_cast<const uint32_t*>(LAs + base + 8 * PITCH + 16);
            }
            #pragma unroll
            for (int ni = 0; ni < 8; ni++) {
                int base = (wn * 64 + ni * 8 + quad) * PITCH + ks * 32 + qlane * 4;
                uint32_t b0 = *reinterpret_cast<const uint32_t*>(LBs + base);
                uint32_t b1 = *reinterpret_cast<const uint32_t*>(LBs + base + 16);
                #pragma unroll
                for (int mi = 0; mi < 4; mi++)
                    MMA16816(acc[mi][ni], a[mi], b0, b1);
            }
        }
    }

    // ---------------- fused epilogue (bias + RMS + RoPE) ----------------
    int part = n0 / IN_F;
    float bv[8][2];
    #pragma unroll
    for (int ni = 0; ni < 8; ni++) {
        int c = n0 + wn * 64 + ni * 8 + qlane * 2;
        bv[ni][0] = bias[c]; bv[ni][1] = bias[c + 1];
    }
    #pragma unroll
    for (int mi = 0; mi < 4; mi++)
        #pragma unroll
        for (int ni = 0; ni < 8; ni++) {
            acc[mi][ni][0] += bv[ni][0]; acc[mi][ni][1] += bv[ni][1];
            acc[mi][ni][2] += bv[ni][0]; acc[mi][ni][3] += bv[ni][1];
        }

    if (part < 2) {
        #pragma unroll
        for (int mi = 0; mi < 4; mi++) {
            float sl = 0.f, sh = 0.f;
            #pragma unroll
            for (int ni = 0; ni < 8; ni++) {
                sl += acc[mi][ni][0] * acc[mi][ni][0] + acc[mi][ni][1] * acc[mi][ni][1];
                sh += acc[mi][ni][2] * acc[mi][ni][2] + acc[mi][ni][3] * acc[mi][ni][3];
            }
            sl += __shfl_xor_sync(~0u, sl, 1); sl += __shfl_xor_sync(~0u, sl, 2);
            sh += __shfl_xor_sync(~0u, sh, 1); sh += __shfl_xor_sync(~0u, sh, 2);
            if (qlane == 0) {
                sSS[(wm * 64 + mi * 16 + quad) * 2 + wn]       = sl;
                sSS[(wm * 64 + mi * 16 + quad + 8) * 2 + wn]   = sh;
            }
        }
    }
    __syncthreads();

    if (part < 2) {
        const float* gg = part ? nk : nq;
        float gv[8][2];
        #pragma unroll
        for (int ni = 0; ni < 8; ni++) {
            int c = wn * 64 + ni * 8 + qlane * 2;
            gv[ni][0] = gg[c]; gv[ni][1] = gg[c + 1];
        }
        #pragma unroll
        for (int mi = 0; mi < 4; mi++) {
            int row = wm * 64 + mi * 16 + quad;
            float sl = sSS[row * 2] + sSS[row * 2 + 1];
            float sh = sSS[(row + 8) * 2] + sSS[(row + 8) * 2 + 1];
            float rl = rsqrtf(sl * (1.0f / 128.0f) + 1e-6f);
            float rh = rsqrtf(sh * (1.0f / 128.0f) + 1e-6f);
            int m = m0 + row;
            #pragma unroll
            for (int ni = 0; ni < 8; ni++) {
                int col = wn * 64 + ni * 8 + qlane * 2;
                float e0 = acc[mi][ni][0] * rl * gv[ni][0];
                float o0 = acc[mi][ni][1] * rl * gv[ni][1];
                float2 cs = *reinterpret_cast<const float2*>(rope + (size_t)m * 128 + col);
                acc[mi][ni][0] = e0 * cs.x - o0 * cs.y;
                acc[mi][ni][1] = e0 * cs.y + o0 * cs.x;
                float e1 = acc[mi][ni][2] * rh * gv[ni][0];
                float o1 = acc[mi][ni][3] * rh * gv[ni][1];
                float2 cs2 = *reinterpret_cast<const float2*>(rope + (size_t)(m + 8) * 128 + col);
                acc[mi][ni][2] = e1 * cs2.x - o1 * cs2.y;
                acc[mi][ni][3] = e1 * cs2.y + o1 * cs2.x;
            }
        }
    }

    #pragma unroll
    for (int mi = 0; mi < 4; mi++) {
        int row = wm * 64 + mi * 16 + quad;
        size_t m = m0 + row;
        #pragma unroll
        for (int ni = 0; ni < 8; ni++) {
            int col = n0 + wn * 64 + ni * 8 + qlane * 2;
            float2 v0 = make_float2(acc[mi][ni][0], acc[mi][ni][1]);
            float2 v1 = make_float2(acc[mi][ni][2], acc[mi][ni][3]);
            *reinterpret_cast<float2*>(out + m * OUT_F + col) = v0;
            *reinterpret_cast<float2*>(out + (m + 8) * OUT_F + col) = v1;
        }
    }
}

extern "C" void kernel_launch(void* const* d_in, const int* in_sizes, int n_in,
                              void* d_out, int out_size) {
    const float *x = 0, *ws = 0, *bias = 0, *ldw = 0, *lu = 0, *smooth = 0;
    const float *nq = 0, *nk = 0, *rope = 0;
    const int* qw = 0;
    for (int i = 0; i < n_in; i++) {
        long s = in_sizes[i];
        const void* p = d_in[i];
        if      (s == 12582912) x      = (const float*)p;
        else if (s == 14155776) qw     = (const int*)p;     // int8 widened to int32
        else if (s == 442368)   ws     = (const float*)p;
        else if (s == 9216)     bias   = (const float*)p;
        else if (s == 98304)    ldw    = (const float*)p;
        else if (s == 294912)   lu     = (const float*)p;
        else if (s == 3072)     smooth = (const float*)p;
        else if (s == 524288)   rope   = (const float*)p;
        else if (s == 128)      { if (!nq) nq = (const float*)p; else nk = (const float*)p; }
    }
    float* out = (float*)d_out;

    static bool attr_set = false;
    if (!attr_set) {
        cudaFuncSetAttribute(gemm_kernel,
            cudaFuncAttributeMaxDynamicSharedMemorySize, SMEM_TOTAL);
        attr_set = true;
    }

    quant_act_kernel<<<MROWS, 384>>>(x, smooth);
    lora_act_kernel<<<MROWS / 32, 256>>>(x, smooth, ldw);
    wdeq_kernel<<<(OUT_F * 192 + 255) / 256, 256>>>(qw);
    wlora_kernel<<<(OUT_F + 255) / 256, 256>>>(lu);
    dummy_kernel<<<1, 32>>>();
    gemm_kernel<<<dim3(OUT_F / TN, MROWS / TM), 256, SMEM_TOTAL>>>(
        ws, bias, nq, nk, rope, out);
}

// round 11
// speedup vs baseline: 1.5673x; 1.5673x over previous
#include <cuda_runtime.h>
#include <cuda_fp16.h>
#include <cstdint>

#define IN_F   3072
#define OUT_F  9216
#define RANK   32
#define KPAD   3104          // 3072 + 32 lora cols; 97 * 32
#define MROWS  4096
#define NCHUNK 97
#define TM     256
#define TN     128

__device__ __half g_A[(size_t)MROWS * KPAD];
__device__ __half g_B[(size_t)OUT_F * KPAD];

__device__ __forceinline__ uint32_t smem_u32(const void* p) {
    uint32_t a;
    asm("{ .reg .u64 t; cvta.to.shared.u64 t, %1; cvt.u32.u64 %0, t; }" : "=r"(a) : "l"(p));
    return a;
}
#define SWZ64(b) ((b) ^ (((b) >> 3) & 0x30))

#define CP16(sa, gp) \
    asm volatile("cp.async.cg.shared.global [%0], [%1], 16;" :: "r"(sa), "l"(gp))
#define CP_COMMIT() asm volatile("cp.async.commit_group;")
#define CP_WAIT0()  asm volatile("cp.async.wait_group 0;")
#define CP_WAIT1()  asm volatile("cp.async.wait_group 1;")

#define LDSM4(r0, r1, r2, r3, a) \
    asm volatile("ldmatrix.sync.aligned.m8n8.x4.shared.b16 {%0,%1,%2,%3}, [%4];" \
        : "=r"(r0), "=r"(r1), "=r"(r2), "=r"(r3) : "r"(a))

#define MMA16816(d, a, b0, b1) \
    asm volatile("mma.sync.aligned.m16n8k16.row.col.f32.f16.f16.f32 " \
        "{%0,%1,%2,%3}, {%4,%5,%6,%7}, {%8,%9}, {%0,%1,%2,%3};" \
        : "+f"((d)[0]), "+f"((d)[1]), "+f"((d)[2]), "+f"((d)[3]) \
        : "r"((a)[0]), "r"((a)[1]), "r"((a)[2]), "r"((a)[3]), "r"(b0), "r"(b1))

// ---------- kernel 1: fused activation group-quant + lora_act --------------
// one block per row m; 384 threads x 8 elements = 3072
__global__ void __launch_bounds__(384) quant_act_kernel(
    const float* __restrict__ x, const float* __restrict__ smooth,
    const float* __restrict__ ldw)
{
    __shared__ float xs_s[IN_F];       // 12 KB raw smoothed row
    __shared__ float red[12][RANK];
    int m = blockIdx.x, t = threadIdx.x;
    const float4* xp = reinterpret_cast<const float4*>(x + (size_t)m * IN_F + t * 8);
    const float4* sp = reinterpret_cast<const float4*>(smooth + t * 8);
    float4 x0 = xp[0], x1 = xp[1], s0 = sp[0], s1 = sp[1];
    float xs[8];
    xs[0] = __fdiv_rn(x0.x, s0.x); xs[1] = __fdiv_rn(x0.y, s0.y);
    xs[2] = __fdiv_rn(x0.z, s0.z); xs[3] = __fdiv_rn(x0.w, s0.w);
    xs[4] = __fdiv_rn(x1.x, s1.x); xs[5] = __fdiv_rn(x1.y, s1.y);
    xs[6] = __fdiv_rn(x1.z, s1.z); xs[7] = __fdiv_rn(x1.w, s1.w);
    #pragma unroll
    for (int i = 0; i < 8; i++) xs_s[t * 8 + i] = xs[i];

    float am = 0.f;
    #pragma unroll
    for (int i = 0; i < 8; i++) am = fmaxf(am, fabsf(xs[i]));
    am = fmaxf(am, __shfl_xor_sync(~0u, am, 1));
    am = fmaxf(am, __shfl_xor_sync(~0u, am, 2));
    am = fmaxf(am, __shfl_xor_sync(~0u, am, 4));
    float ascale = fmaxf(__fdiv_rn(am, 7.0f), 1e-8f);
    union { uint4 u; __half h[8]; } o;
    #pragma unroll
    for (int i = 0; i < 8; i++) {
        float q = rintf(__fdiv_rn(xs[i], ascale));
        q = fminf(fmaxf(q, -8.f), 7.f);
        o.h[i] = __float2half_rn(q * ascale);
    }
    *reinterpret_cast<uint4*>(g_A + (size_t)m * KPAD + t * 8) = o.u;

    // ---- lora_act: xs_row @ lora_down (3072x32) ----
    __syncthreads();
    int r = t & 31, slice = t >> 5;        // 12 slices x 256 k
    const float* lp = ldw + (size_t)(slice * 256) * RANK + r;
    const float* xp2 = xs_s + slice * 256;
    float acc = 0.f;
    #pragma unroll 8
    for (int k = 0; k < 256; k++) acc += xp2[k] * lp[(size_t)k * RANK];
    red[slice][r] = acc;
    __syncthreads();
    if (t < RANK) {
        float s = 0.f;
        #pragma unroll
        for (int j = 0; j < 12; j++) s += red[j][t];
        g_A[(size_t)m * KPAD + IN_F + t] = __float2half_rn(s);
    }
}

// ---------- kernel 2: weight int4 dequant (int32 input) -> fp16 ------------
__global__ void __launch_bounds__(256) wdeq_kernel(
    const int* __restrict__ qw, const float* __restrict__ ws)
{
    int tid = blockIdx.x * blockDim.x + threadIdx.x;
    if (tid >= OUT_F * 192) return;
    int n = tid / 192, c = tid - n * 192, k0 = c * 16;
    const int4* q4 = reinterpret_cast<const int4*>(qw + (size_t)n * (IN_F / 2) + c * 8);
    int4 v0 = q4[0], v1 = q4[1];
    int vals[8] = {v0.x, v0.y, v0.z, v0.w, v1.x, v1.y, v1.z, v1.w};
    float scale = ws[(k0 >> 6) * OUT_F + n];
    union { uint4 u[2]; __half h[16]; } o;
    #pragma unroll
    for (int j = 0; j < 8; j++) {
        int b  = vals[j];
        int lo = ((b & 15) ^ 8) - 8;
        int hi = b >> 4;
        o.h[2*j]   = __float2half_rn((float)lo * scale);
        o.h[2*j+1] = __float2half_rn((float)hi * scale);
    }
    uint4* dst = reinterpret_cast<uint4*>(g_B + (size_t)n * KPAD + k0);
    dst[0] = o.u[0]; dst[1] = o.u[1];
}

// ---------- kernel 3: lora_up -> B pad cols (vectorized) --------------------
__global__ void __launch_bounds__(256) wlora_kernel(const float* __restrict__ lu)
{
    int n = blockIdx.x * blockDim.x + threadIdx.x;
    if (n >= OUT_F) return;
    const float4* src = reinterpret_cast<const float4*>(lu + (size_t)n * RANK);
    union { uint4 u[4]; __half h[32]; } o;
    #pragma unroll
    for (int i = 0; i < 8; i++) {
        float4 v = src[i];
        o.h[4*i+0] = __float2half_rn(v.x); o.h[4*i+1] = __float2half_rn(v.y);
        o.h[4*i+2] = __float2half_rn(v.z); o.h[4*i+3] = __float2half_rn(v.w);
    }
    uint4* dst = reinterpret_cast<uint4*>(g_B + (size_t)n * KPAD + IN_F);
    #pragma unroll
    for (int i = 0; i < 4; i++) dst[i] = o.u[i];
}

// ---------- kernel 4: mma.sync GEMM 256x128 + fused bias/RMS/RoPE ----------
// 256 threads, 8 warps (4M x 2N), warp tile 64x64, K-chunk 32, double-buffered.
__global__ void __launch_bounds__(256, 1) gemm_kernel(
    const float* __restrict__ bias, const float* __restrict__ nq,
    const float* __restrict__ nk,   const float* __restrict__ rope,
    float* __restrict__ out)
{
    __shared__ __align__(128) uint8_t smA[2][TM * 64];   // 2 x 16KB
    __shared__ __align__(128) uint8_t smB[2][TN * 64];   // 2 x 8KB
    __shared__ float ss_s[TM][2];

    int t = threadIdx.x, wid = t >> 5, lane = t & 31;
    int wm = wid >> 1, wn = wid & 1;
    int quad = lane >> 2, qlane = lane & 3;
    int n0 = blockIdx.x * TN, m0 = blockIdx.y * TM;

    uint32_t sbA = smem_u32(smA), sbB = smem_u32(smB);
    const __half* Ag = g_A + (size_t)m0 * KPAD;
    const __half* Bg = g_B + (size_t)n0 * KPAD;

    uint32_t soA[4], soB[2];
    size_t goA[4], goB[2];
    #pragma unroll
    for (int i = 0; i < 4; i++) {
        int seg = i * 256 + t, row = seg >> 2, s = seg & 3;
        soA[i] = SWZ64((uint32_t)(row * 64 + s * 16));
        goA[i] = (size_t)row * KPAD + s * 8;
    }
    #pragma unroll
    for (int i = 0; i < 2; i++) {
        int seg = i * 256 + t, row = seg >> 2, s = seg & 3;
        soB[i] = SWZ64((uint32_t)(row * 64 + s * 16));
        goB[i] = (size_t)row * KPAD + s * 8;
    }

    float acc[4][8][4];
    #pragma unroll
    for (int mi = 0; mi < 4; mi++)
        #pragma unroll
        for (int ni = 0; ni < 8; ni++)
            #pragma unroll
            for (int j = 0; j < 4; j++) acc[mi][ni][j] = 0.f;

    #pragma unroll
    for (int i = 0; i < 4; i++) CP16(sbA + soA[i], Ag + goA[i]);
    #pragma unroll
    for (int i = 0; i < 2; i++) CP16(sbB + soB[i], Bg + goB[i]);
    CP_COMMIT();

    int buf = 0;
    for (int kt = 0; kt < NCHUNK; kt++) {
        if (kt + 1 < NCHUNK) {
            uint32_t ab = sbA + (buf ^ 1) * (TM * 64);
            uint32_t bb = sbB + (buf ^ 1) * (TN * 64);
            int ko = (kt + 1) * 32;
            #pragma unroll
            for (int i = 0; i < 4; i++) CP16(ab + soA[i], Ag + goA[i] + ko);
            #pragma unroll
            for (int i = 0; i < 2; i++) CP16(bb + soB[i], Bg + goB[i] + ko);
            CP_COMMIT();
            CP_WAIT1();
        } else {
            CP_WAIT0();
        }
        __syncthreads();

        uint32_t aBase = sbA + buf * (TM * 64);
        uint32_t bBase = sbB + buf * (TN * 64);
        #pragma unroll
        for (int ks = 0; ks < 2; ks++) {
            uint32_t a[4][4];
            #pragma unroll
            for (int mi = 0; mi < 4; mi++) {
                int row = wm * 64 + mi * 16 + ((lane >> 3) & 1) * 8 + (lane & 7);
                int kh  = ks * 2 + (lane >> 4);
                LDSM4(a[mi][0], a[mi][1], a[mi][2], a[mi][3],
                      aBase + SWZ64((uint32_t)(row * 64 + kh * 16)));
            }
            uint32_t bf[4][4];
            #pragma unroll
            for (int nj = 0; nj < 4; nj++) {
                int row = wn * 64 + nj * 16 + ((lane >> 4) & 1) * 8 + (lane & 7);
                int kh  = ks * 2 + ((lane >> 3) & 1);
                LDSM4(bf[nj][0], bf[nj][1], bf[nj][2], bf[nj][3],
                      bBase + SWZ64((uint32_t)(row * 64 + kh * 16)));
            }
            #pragma unroll
            for (int mi = 0; mi < 4; mi++)
                #pragma unroll
                for (int ni = 0; ni < 8; ni++)
                    MMA16816(acc[mi][ni], a[mi],
                             bf[ni >> 1][(ni & 1) * 2], bf[ni >> 1][(ni & 1) * 2 + 1]);
        }
        __syncthreads();
        buf ^= 1;
    }

    // ---------------- fused epilogue ----------------
    int part = n0 / IN_F;     // 0=q, 1=k, 2=v (tile N == one head of 128)
    float bv[8][2];
    #pragma unroll
    for (int ni = 0; ni < 8; ni++) {
        int c = n0 + wn * 64 + ni * 8 + qlane * 2;
        bv[ni][0] = bias[c]; bv[ni][1] = bias[c + 1];
    }
    #pragma unroll
    for (int mi = 0; mi < 4; mi++)
        #pragma unroll
        for (int ni = 0; ni < 8; ni++) {
            acc[mi][ni][0] += bv[ni][0]; acc[mi][ni][1] += bv[ni][1];
            acc[mi][ni][2] += bv[ni][0]; acc[mi][ni][3] += bv[ni][1];
        }

    if (part < 2) {
        #pragma unroll
        for (int mi = 0; mi < 4; mi++) {
            float sl = 0.f, sh = 0.f;
            #pragma unroll
            for (int ni = 0; ni < 8; ni++) {
                sl += acc[mi][ni][0] * acc[mi][ni][0] + acc[mi][ni][1] * acc[mi][ni][1];
                sh += acc[mi][ni][2] * acc[mi][ni][2] + acc[mi][ni][3] * acc[mi][ni][3];
            }
            sl += __shfl_xor_sync(~0u, sl, 1); sl += __shfl_xor_sync(~0u, sl, 2);
            sh += __shfl_xor_sync(~0u, sh, 1); sh += __shfl_xor_sync(~0u, sh, 2);
            if (qlane == 0) {
                ss_s[wm * 64 + mi * 16 + quad][wn]     = sl;
                ss_s[wm * 64 + mi * 16 + quad + 8][wn] = sh;
            }
        }
    }
    __syncthreads();

    if (part < 2) {
        const float* g = part ? nk : nq;
        float gv[8][2];
        #pragma unroll
        for (int ni = 0; ni < 8; ni++) {
            int c = wn * 64 + ni * 8 + qlane * 2;
            gv[ni][0] = g[c]; gv[ni][1] = g[c + 1];
        }
        #pragma unroll
        for (int mi = 0; mi < 4; mi++) {
            int row = wm * 64 + mi * 16 + quad;
            float sl = ss_s[row][0] + ss_s[row][1];
            float sh = ss_s[row + 8][0] + ss_s[row + 8][1];
            float rl = rsqrtf(sl * (1.0f / 128.0f) + 1e-6f);
            float rh = rsqrtf(sh * (1.0f / 128.0f) + 1e-6f);
            int m = m0 + row;
            #pragma unroll
            for (int ni = 0; ni < 8; ni++) {
                int col = wn * 64 + ni * 8 + qlane * 2;
                float e0 = acc[mi][ni][0] * rl * gv[ni][0];
                float o0 = acc[mi][ni][1] * rl * gv[ni][1];
                float2 cs = *reinterpret_cast<const float2*>(rope + (size_t)m * 128 + col);
                acc[mi][ni][0] = e0 * cs.x - o0 * cs.y;
                acc[mi][ni][1] = e0 * cs.y + o0 * cs.x;
                float e1 = acc[mi][ni][2] * rh * gv[ni][0];
                float o1 = acc[mi][ni][3] * rh * gv[ni][1];
                float2 cs2 = *reinterpret_cast<const float2*>(rope + (size_t)(m + 8) * 128 + col);
                acc[mi][ni][2] = e1 * cs2.x - o1 * cs2.y;
                acc[mi][ni][3] = e1 * cs2.y + o1 * cs2.x;
            }
        }
    }

    #pragma unroll
    for (int mi = 0; mi < 4; mi++) {
        int row = wm * 64 + mi * 16 + quad;
        size_t m = m0 + row;
        #pragma unroll
        for (int ni = 0; ni < 8; ni++) {
            int col = n0 + wn * 64 + ni * 8 + qlane * 2;
            float2 v0 = make_float2(acc[mi][ni][0], acc[mi][ni][1]);
            float2 v1 = make_float2(acc[mi][ni][2], acc[mi][ni][3]);
            *reinterpret_cast<float2*>(out + m * OUT_F + col) = v0;
            *reinterpret_cast<float2*>(out + (m + 8) * OUT_F + col) = v1;
        }
    }
}

extern "C" void kernel_launch(void* const* d_in, const int* in_sizes, int n_in,
                              void* d_out, int out_size) {
    const float *x = 0, *ws = 0, *bias = 0, *ldw = 0, *lu = 0, *smooth = 0;
    const float *nq = 0, *nk = 0, *rope = 0;
    const int* qw = 0;
    for (int i = 0; i < n_in; i++) {
        long s = in_sizes[i];
        const void* p = d_in[i];
        if      (s == 12582912) x      = (const float*)p;
        else if (s == 14155776) qw     = (const int*)p;     // int8 widened to int32
        else if (s == 442368)   ws     = (const float*)p;
        else if (s == 9216)     bias   = (const float*)p;
        else if (s == 98304)    ldw    = (const float*)p;
        else if (s == 294912)   lu     = (const float*)p;
        else if (s == 3072)     smooth = (const float*)p;
        else if (s == 524288)   rope   = (const float*)p;
        else if (s == 128)      { if (!nq) nq = (const float*)p; else nk = (const float*)p; }
    }
    float* out = (float*)d_out;

    quant_act_kernel<<<MROWS, 384>>>(x, smooth, ldw);
    wdeq_kernel<<<(OUT_F * 192 + 255) / 256, 256>>>(qw, ws);
    wlora_kernel<<<(OUT_F + 255) / 256, 256>>>(lu);
    gemm_kernel<<<dim3(OUT_F / TN, MROWS / TM), 256>>>(bias, nq, nk, rope, out);
}